// round 10
// baseline (speedup 1.0000x reference)
#include <cuda_runtime.h>
#include <cuda_fp16.h>
#include <cstdint>

// Layout after transpose: per point n, 256 bytes = 16 chunks of 16B.
// Chunk f (f=0..15) = [ x(4f..4f+3) | y(4f..4f+3) ]  (8 halves).
// One edge endpoint = one contiguous 256B row = one LDG.128 across 16 lanes.
#define MAX_N 100000
__device__ __align__(256) __half2 g_buf[(size_t)MAX_N * 64];
__device__ int g_is64;

// ---------------- f32x2 / sqrt.approx helpers ----------------
__device__ __forceinline__ unsigned long long fma2(unsigned long long a,
                                                   unsigned long long b,
                                                   unsigned long long c) {
    unsigned long long r;
    asm("fma.rn.f32x2 %0, %1, %2, %3;" : "=l"(r) : "l"(a), "l"(b), "l"(c));
    return r;
}
__device__ __forceinline__ void upk(unsigned long long v, float& a, float& b) {
    asm("mov.b64 {%0, %1}, %2;" : "=f"(a), "=f"(b) : "l"(v));
}
__device__ __forceinline__ unsigned long long pk(float a, float b) {
    unsigned long long r;
    asm("mov.b64 %0, {%1, %2};" : "=l"(r) : "f"(a), "f"(b));
    return r;
}
__device__ __forceinline__ float sqapx(float x) {
    float r;
    asm("sqrt.approx.f32 %0, %1;" : "=f"(r) : "f"(x));
    return r;
}

// ---------------- Kernel 1: transpose [64, N] float2 -> chunked half ----
__global__ void __launch_bounds__(256) transpose_kernel(
    const float2* __restrict__ in, const unsigned* __restrict__ skel_raw,
    float* out, int N) {
    if (blockIdx.x == 0 && threadIdx.x < 32) {
        unsigned v = skel_raw[2 * threadIdx.x + 1] | skel_raw[2 * (threadIdx.x + 32) + 1];
        unsigned b = __ballot_sync(0xffffffffu, v == 0u);
        if (threadIdx.x == 0) {
            g_is64 = (b == 0xffffffffu);
            out[0] = 0.0f;
        }
    }

    __shared__ float2 tile[64][33];
    int n0 = blockIdx.x * 32;
    int tx = threadIdx.x & 31;
    int ty = threadIdx.x >> 5;
    int c = n0 + tx;
    if (c < N) {
#pragma unroll
        for (int i = 0; i < 8; ++i) {
            int b = ty + i * 8;  // frame index 0..63
            tile[b][tx] = __ldcs(&in[(size_t)b * N + c]);
        }
    }
    __syncthreads();
#pragma unroll
    for (int k = 0; k < 4; ++k) {
        int l = threadIdx.x + k * 256;
        int bp = l & 31;      // frame pair: frames 2bp, 2bp+1
        int cc = l >> 5;      // point within block
        int n = n0 + cc;
        if (n < N) {
            float2 v0 = tile[2 * bp][cc];
            float2 v1 = tile[2 * bp + 1][cc];
            char* base = (char*)g_buf + (size_t)n * 256 + (bp >> 1) * 16 + (bp & 1) * 4;
            *(__half2*)(base)     = __floats2half2_rn(v0.x, v1.x);  // x pair
            *(__half2*)(base + 8) = __floats2half2_rn(v0.y, v1.y);  // y pair
        }
    }
}

// ---------------- Kernel 2: main loss ----------------
// Warp = 2 edges (16 lanes each). Lane covers 4 frames via ONE uint4 chunk
// per endpoint => 2 LDG.128 per warp-iter. DEPTH-3 register pipeline:
// while computing quad p, gathers for p+nw and p+2nw are in flight and
// indices for p+3nw are loading. #pragma unroll 2 lets ptxas rename the
// rotation instead of emitting MOVs. Tail branch-free via clamped loads.

struct Pair { int s0, s1; float c; };
struct GatherC { uint4 a, b; };  // 8 regs

__device__ __forceinline__ Pair load_idx(const void* skel_raw,
                                         const float* init_len,
                                         int e, int E, bool is64) {
    Pair q;
    int ec = e < E ? e : (E - 1);
    if (is64) {
        longlong2 s = ((const longlong2*)skel_raw)[ec];
        q.s0 = (int)s.x;
        q.s1 = (int)s.y;
    } else {
        int2 s = ((const int2*)skel_raw)[ec];
        q.s0 = s.x;
        q.s1 = s.y;
    }
    q.c = init_len[ec];
    if (e >= E) { q.s0 = 0; q.s1 = 0; q.c = 0.0f; }
    return q;
}

__device__ __forceinline__ GatherC issue_gather(const char* tb, Pair q) {
    GatherC g;
    g.a = *(const uint4*)(tb + (unsigned)q.s0 * 256u);
    g.b = *(const uint4*)(tb + (unsigned)q.s1 * 256u);
    return g;
}

__global__ void __launch_bounds__(256, 5) loss_kernel(
    const void* __restrict__ skel_raw, const float* __restrict__ init_len,
    float* out, int E, float invE) {
    const unsigned long long NEG1 = 0xBF800000BF800000ULL;  // (-1.f, -1.f)
    int lane = threadIdx.x & 31;
    int half = lane >> 4;      // which of 2 edges in warp
    int el = lane & 15;        // chunk index within row
    int warp = (blockIdx.x * blockDim.x + threadIdx.x) >> 5;
    int nwarps = (gridDim.x * blockDim.x) >> 5;
    int P = (E + 1) >> 1;
    bool is64 = (g_is64 != 0);
    const char* tb = (const char*)g_buf + (unsigned)el * 16u;

    unsigned long long acc = 0ull;

    // Depth-3 prologue: gathers for p and p+nw in flight; indices for p+2nw.
    int p = warp;
    Pair q0 = load_idx(skel_raw, init_len, 2 * p + half, E, is64);
    GatherC g0 = issue_gather(tb, q0);
    Pair q1 = load_idx(skel_raw, init_len, 2 * (p + nwarps) + half, E, is64);
    GatherC g1 = issue_gather(tb, q1);
    Pair q2 = load_idx(skel_raw, init_len, 2 * (p + 2 * nwarps) + half, E, is64);

#pragma unroll 2
    for (; p < P; p += nwarps) {
        // Issue the gather two iterations ahead (indices already resident).
        GatherC g2 = issue_gather(tb, q2);
        // Load indices three iterations ahead.
        Pair q3 = load_idx(skel_raw, init_len,
                           2 * (p + 3 * nwarps) + half, E, is64);

        // Compute on the oldest stage (in flight for ~2 iterations).
        unsigned long long cc2 = pk(q0.c, q0.c);
        const __half2* A = (const __half2*)&g0.a;  // [x01, x23, y01, y23]
        const __half2* B = (const __half2*)&g0.b;
        __half2 dx01 = __hsub2(A[0], B[0]);
        __half2 dx23 = __hsub2(A[1], B[1]);
        __half2 dy01 = __hsub2(A[2], B[2]);
        __half2 dy23 = __hsub2(A[3], B[3]);
        __half2 t01 = __hfma2(dy01, dy01, __hmul2(dx01, dx01));
        __half2 t23 = __hfma2(dy23, dy23, __hmul2(dx23, dx23));
        float2 f01 = __half22float2(t01);
        float2 f23 = __half22float2(t23);
        unsigned long long len0 = pk(sqapx(f01.x), sqapx(f01.y));
        unsigned long long len1 = pk(sqapx(f23.x), sqapx(f23.y));
        unsigned long long d0 = fma2(cc2, NEG1, len0);
        unsigned long long d1 = fma2(cc2, NEG1, len1);
        acc = fma2(d0, d0, acc);
        acc = fma2(d1, d1, acc);

        // Rotate pipeline (renamed away under unroll).
        q0 = q1; q1 = q2; q2 = q3;
        g0 = g1; g1 = g2;
    }

    float a0, a1;
    upk(acc, a0, a1);
    float s = a0 + a1;
#pragma unroll
    for (int off = 16; off; off >>= 1)
        s += __shfl_down_sync(0xffffffffu, s, off);

    __shared__ float warp_sums[8];
    if (lane == 0) warp_sums[threadIdx.x >> 5] = s;
    __syncthreads();
    if (threadIdx.x < 8) {
        float v = warp_sums[threadIdx.x];
#pragma unroll
        for (int off = 4; off; off >>= 1)
            v += __shfl_down_sync(0xffu, v, off);
        if (threadIdx.x == 0) atomicAdd(out, v * invE);
    }
}

extern "C" void kernel_launch(void* const* d_in, const int* in_sizes, int n_in,
                              void* d_out, int out_size) {
    const float2* pts = (const float2*)d_in[0];
    const void* skel = d_in[1];
    const float* initl = (const float*)d_in[2];
    float* out = (float*)d_out;

    int N = in_sizes[0] / 128;  // B=64 frames, 2 coords
    int E = in_sizes[2];

    transpose_kernel<<<(N + 31) / 32, 256>>>(pts, (const unsigned*)skel, out, N);
    loss_kernel<<<740, 256>>>(skel, initl, out, E, 1.0f / (float)E);
}

// round 12
// speedup vs baseline: 1.0014x; 1.0014x over previous
#include <cuda_runtime.h>
#include <cuda_fp16.h>
#include <cstdint>

// Layout after transpose: per point n, 256 bytes = 16 chunks of 16B.
// Chunk f (f=0..15) = [ x(4f..4f+3) | y(4f..4f+3) ]  (8 halves).
// One edge endpoint = one contiguous 256B row = one LDG.128 across 16 lanes.
#define MAX_N 100000
#define E_MAX 200000
#define E_PAD 240000   // >= E + 4*nwarps + margin; padded records contribute 0
__device__ __align__(256) __half2 g_buf[(size_t)MAX_N * 64];
// Edge record: {s0*256, s1*256, __float_as_uint(c), 0}
__device__ __align__(16) uint4 g_edges[E_PAD];

// ---------------- f32x2 / sqrt.approx helpers ----------------
__device__ __forceinline__ unsigned long long fma2(unsigned long long a,
                                                   unsigned long long b,
                                                   unsigned long long c) {
    unsigned long long r;
    asm("fma.rn.f32x2 %0, %1, %2, %3;" : "=l"(r) : "l"(a), "l"(b), "l"(c));
    return r;
}
__device__ __forceinline__ void upk(unsigned long long v, float& a, float& b) {
    asm("mov.b64 {%0, %1}, %2;" : "=f"(a), "=f"(b) : "l"(v));
}
__device__ __forceinline__ unsigned long long pk(float a, float b) {
    unsigned long long r;
    asm("mov.b64 %0, {%1, %2};" : "=l"(r) : "f"(a), "f"(b));
    return r;
}
__device__ __forceinline__ float sqapx(float x) {
    float r;
    asm("sqrt.approx.f32 %0, %1;" : "=f"(r) : "f"(x));
    return r;
}

// ---------------- Kernel 1: transpose + edge-record prep ----------------
// Blocks [0, tblocks): transpose [64, N] float2 -> chunked half g_buf.
// Blocks [tblocks, ...): convert skeleton (int64 OR int32) + init_len into
// padded pre-scaled records in g_edges. Per-block dtype detection via ballot
// (indices < 100000 => int64 stores have all-zero odd words).
__global__ void __launch_bounds__(256) transpose_kernel(
    const float2* __restrict__ in, const unsigned* __restrict__ skel_raw,
    const float* __restrict__ init_len, float* out, int N, int E, int tblocks) {
    if (blockIdx.x >= tblocks) {
        // ---- prep branch ----
        __shared__ int sh_is64;
        if (threadIdx.x < 32) {
            unsigned v = skel_raw[2 * threadIdx.x + 1] |
                         skel_raw[2 * (threadIdx.x + 32) + 1];
            unsigned b = __ballot_sync(0xffffffffu, v == 0u);
            if (threadIdx.x == 0) sh_is64 = (b == 0xffffffffu);
        }
        __syncthreads();
        int is64 = sh_is64;
        int e = (blockIdx.x - tblocks) * 256 + threadIdx.x;
        if (e == 0) out[0] = 0.0f;
        if (e < E_PAD) {
            uint4 r = make_uint4(0u, 0u, 0u, 0u);
            if (e < E) {
                int s0, s1;
                if (is64) {
                    longlong2 s = ((const longlong2*)skel_raw)[e];
                    s0 = (int)s.x; s1 = (int)s.y;
                } else {
                    int2 s = ((const int2*)skel_raw)[e];
                    s0 = s.x; s1 = s.y;
                }
                r.x = (unsigned)s0 * 256u;
                r.y = (unsigned)s1 * 256u;
                r.z = __float_as_uint(init_len[e]);
            }
            g_edges[e] = r;
        }
        return;
    }

    // ---- transpose branch ----
    __shared__ float2 tile[64][33];
    int n0 = blockIdx.x * 32;
    int tx = threadIdx.x & 31;
    int ty = threadIdx.x >> 5;
    int c = n0 + tx;
    if (c < N) {
#pragma unroll
        for (int i = 0; i < 8; ++i) {
            int b = ty + i * 8;  // frame index 0..63
            tile[b][tx] = __ldcs(&in[(size_t)b * N + c]);
        }
    }
    __syncthreads();
#pragma unroll
    for (int k = 0; k < 4; ++k) {
        int l = threadIdx.x + k * 256;
        int bp = l & 31;      // frame pair: frames 2bp, 2bp+1
        int cc = l >> 5;      // point within block
        int n = n0 + cc;
        if (n < N) {
            float2 v0 = tile[2 * bp][cc];
            float2 v1 = tile[2 * bp + 1][cc];
            char* base = (char*)g_buf + (size_t)n * 256 + (bp >> 1) * 16 + (bp & 1) * 4;
            *(__half2*)(base)     = __floats2half2_rn(v0.x, v1.x);  // x pair
            *(__half2*)(base + 8) = __floats2half2_rn(v0.y, v1.y);  // y pair
        }
    }
}

// ---------------- Kernel 2: main loss ----------------
// Warp = 2 edges (16 lanes each). Lane covers 4 frames via ONE uint4 chunk
// per endpoint => 2 gather LDG.128 + 1 record LDG.128 per warp-iter.
// Depth-2 register pipeline; records are pre-scaled so the loop has no
// dtype branch, no clamp, no scaling IMADs. Padded records contribute 0.

struct Rec { unsigned o0, o1; float c; };
struct GatherC { uint4 a, b; };  // 8 regs

__device__ __forceinline__ Rec load_rec(int e) {
    uint4 r = g_edges[e];
    Rec q;
    q.o0 = r.x;
    q.o1 = r.y;
    q.c = __uint_as_float(r.z);
    return q;
}

__device__ __forceinline__ GatherC issue_gather(const char* tb, Rec q) {
    GatherC g;
    g.a = *(const uint4*)(tb + q.o0);
    g.b = *(const uint4*)(tb + q.o1);
    return g;
}

__global__ void __launch_bounds__(256, 6) loss_kernel(
    float* out, int E, float invE) {
    const unsigned long long NEG1 = 0xBF800000BF800000ULL;  // (-1.f, -1.f)
    int lane = threadIdx.x & 31;
    int half = lane >> 4;      // which of 2 edges in warp
    int el = lane & 15;        // chunk index within row
    int warp = (blockIdx.x * blockDim.x + threadIdx.x) >> 5;
    int nwarps = (gridDim.x * blockDim.x) >> 5;
    int P = (E + 1) >> 1;
    const char* tb = (const char*)g_buf + (unsigned)el * 16u;

    unsigned long long acc = 0ull;

    // Depth-2 prologue: record+gathers for p; record for p+nw.
    int p = warp;
    Rec qc = load_rec(2 * p + half);
    GatherC gc = issue_gather(tb, qc);
    Rec qn = load_rec(2 * (p + nwarps) + half);

#pragma unroll 2
    for (; p < P; p += nwarps) {
        // Issue next iteration's gathers (record already resident).
        GatherC gn = issue_gather(tb, qn);
        // Load record two iterations ahead (always in-bounds: E_PAD pad).
        Rec qf = load_rec(2 * (p + 2 * nwarps) + half);

        // Compute on current gathers (in flight since previous iteration).
        unsigned long long cc2 = pk(qc.c, qc.c);
        const __half2* A = (const __half2*)&gc.a;  // [x01, x23, y01, y23]
        const __half2* B = (const __half2*)&gc.b;
        __half2 dx01 = __hsub2(A[0], B[0]);
        __half2 dx23 = __hsub2(A[1], B[1]);
        __half2 dy01 = __hsub2(A[2], B[2]);
        __half2 dy23 = __hsub2(A[3], B[3]);
        __half2 t01 = __hfma2(dy01, dy01, __hmul2(dx01, dx01));
        __half2 t23 = __hfma2(dy23, dy23, __hmul2(dx23, dx23));
        float2 f01 = __half22float2(t01);
        float2 f23 = __half22float2(t23);
        unsigned long long len0 = pk(sqapx(f01.x), sqapx(f01.y));
        unsigned long long len1 = pk(sqapx(f23.x), sqapx(f23.y));
        unsigned long long d0 = fma2(cc2, NEG1, len0);
        unsigned long long d1 = fma2(cc2, NEG1, len1);
        acc = fma2(d0, d0, acc);
        acc = fma2(d1, d1, acc);

        // Rotate (renamed under unroll).
        qc = qn;
        qn = qf;
        gc = gn;
    }

    float a0, a1;
    upk(acc, a0, a1);
    float s = a0 + a1;
#pragma unroll
    for (int off = 16; off; off >>= 1)
        s += __shfl_down_sync(0xffffffffu, s, off);

    __shared__ float warp_sums[8];
    if (lane == 0) warp_sums[threadIdx.x >> 5] = s;
    __syncthreads();
    if (threadIdx.x < 8) {
        float v = warp_sums[threadIdx.x];
#pragma unroll
        for (int off = 4; off; off >>= 1)
            v += __shfl_down_sync(0xffu, v, off);
        if (threadIdx.x == 0) atomicAdd(out, v * invE);
    }
}

extern "C" void kernel_launch(void* const* d_in, const int* in_sizes, int n_in,
                              void* d_out, int out_size) {
    const float2* pts = (const float2*)d_in[0];
    const void* skel = d_in[1];
    const float* initl = (const float*)d_in[2];
    float* out = (float*)d_out;

    int N = in_sizes[0] / 128;  // B=64 frames, 2 coords
    int E = in_sizes[2];

    int tblocks = (N + 31) / 32;
    int pblocks = (E_PAD + 255) / 256;
    transpose_kernel<<<tblocks + pblocks, 256>>>(
        pts, (const unsigned*)skel, initl, out, N, E, tblocks);
    loss_kernel<<<888, 256>>>(out, E, 1.0f / (float)E);
}